// round 2
// baseline (speedup 1.0000x reference)
#include <cuda_runtime.h>
#include <cuda_bf16.h>
#include <cstdint>

// Problem: x (C,H,W) fp32, N = C*H*W = 12288.
// lo = relu(EPS - x)*0.5 ; hi = relu(x - (1-EPS))*0.5
// center = x + lo - hi ; err = EPS - lo - hi ; cond = err >= 0
// out row 0 = center (flattened). Selected element k (in row-major order)
// gets out[rank_k, k] = err_k where rank_k = inclusive cumsum of cond.
// Everything else is zero. Output shape (1+N, N).

#define EPSV 0.1f
#define NTHREADS 1024

__global__ void __launch_bounds__(NTHREADS, 1)
scatter_kernel(const float* __restrict__ x, float* __restrict__ out, int N) {
    __shared__ int s_cnt[NTHREADS];

    const int t = threadIdx.x;
    const int items = (N + NTHREADS - 1) / NTHREADS;   // 12 for N=12288
    const int base  = t * items;

    // Pass 1: compute center (write row 0), count selected in my chunk.
    int cnt = 0;
    for (int j = 0; j < items; ++j) {
        int i = base + j;
        if (i < N) {
            float xv = x[i];
            float lo = fmaxf(EPSV - xv, 0.0f) * 0.5f;
            float hi = fmaxf(xv - (1.0f - EPSV), 0.0f) * 0.5f;
            float center = xv + lo - hi;
            float err    = EPSV - lo - hi;
            out[i] = center;               // row 0
            cnt += (err >= 0.0f) ? 1 : 0;
        }
    }
    s_cnt[t] = cnt;
    __syncthreads();

    // Inclusive block scan (Hillis-Steele) over per-thread counts.
    for (int off = 1; off < NTHREADS; off <<= 1) {
        int v = (t >= off) ? s_cnt[t - off] : 0;
        __syncthreads();
        s_cnt[t] += v;
        __syncthreads();
    }
    int excl = s_cnt[t] - cnt;  // exclusive prefix for this thread's chunk

    // Pass 2: recompute err, scatter selected entries to their rows.
    int rank = 1 + excl;        // rows start at 1
    for (int j = 0; j < items; ++j) {
        int i = base + j;
        if (i < N) {
            float xv = x[i];
            float lo = fmaxf(EPSV - xv, 0.0f) * 0.5f;
            float hi = fmaxf(xv - (1.0f - EPSV), 0.0f) * 0.5f;
            float err = EPSV - lo - hi;
            if (err >= 0.0f) {
                out[(size_t)rank * (size_t)N + (size_t)i] = err;
                ++rank;
            }
        }
    }
}

extern "C" void kernel_launch(void* const* d_in, const int* in_sizes, int n_in,
                              void* d_out, int out_size) {
    const float* x = (const float*)d_in[0];
    float* out = (float*)d_out;
    int N = in_sizes[0];        // 12288

    // Zero the whole (1+N, N) output — this is the 604 MB that dominates.
    cudaMemsetAsync(d_out, 0, (size_t)out_size * sizeof(float));

    // Single block computes scan + writes row 0 and scattered err entries.
    scatter_kernel<<<1, NTHREADS>>>(x, out, N);
}